// round 8
// baseline (speedup 1.0000x reference)
#include <cuda_runtime.h>
#include <cuda_bf16.h>
#include <cuda_fp16.h>
#include <cstdint>

#define ROWS_TOTAL 16384
#define DMODEL 256

// ---------------------------------------------------------------------------
// Scratch (static device arrays — no allocation in kernel_launch).
// ---------------------------------------------------------------------------
__device__ __align__(16) float  g_Qh[ROWS_TOTAL * DMODEL];
__device__ __align__(16) float  g_AV[ROWS_TOTAL * DMODEL];
__device__ __align__(16) __half g_Khh[ROWS_TOTAL * DMODEL];
__device__ __align__(16) __half g_Vhh[ROWS_TOTAL * DMODEL];
// Transposed + bf16-split weights: [mat][N=256][K=256]
__device__ __align__(16) __nv_bfloat16 g_Wth[4 * 65536];
__device__ __align__(16) __nv_bfloat16 g_Wtl[4 * 65536];

// ---------------------------------------------------------------------------
// Warp-level tensor-core primitives (base-target: ldmatrix sm_75+, bf16 mma sm_80+)
// ---------------------------------------------------------------------------
__device__ __forceinline__ uint32_t smem_to_u32(const void* smem_ptr) {
    uint32_t addr;
    asm("{ .reg .u64 tmp; cvta.to.shared.u64 tmp, %1; cvt.u32.u64 %0, tmp; }"
        : "=r"(addr) : "l"(smem_ptr));
    return addr;
}

#define LDMATRIX_X4(r0, r1, r2, r3, addr) \
    asm volatile("ldmatrix.sync.aligned.m8n8.x4.shared.b16 {%0,%1,%2,%3}, [%4];" \
                 : "=r"(r0), "=r"(r1), "=r"(r2), "=r"(r3) : "r"(addr))

#define LDMATRIX_X2(r0, r1, addr) \
    asm volatile("ldmatrix.sync.aligned.m8n8.x2.shared.b16 {%0,%1}, [%2];" \
                 : "=r"(r0), "=r"(r1) : "r"(addr))

#define MMA_BF16(d, a, b) \
    asm volatile("mma.sync.aligned.m16n8k16.row.col.f32.bf16.bf16.f32 " \
                 "{%0,%1,%2,%3}, {%4,%5,%6,%7}, {%8,%9}, {%0,%1,%2,%3};" \
                 : "+f"((d)[0]), "+f"((d)[1]), "+f"((d)[2]), "+f"((d)[3]) \
                 : "r"((a)[0]), "r"((a)[1]), "r"((a)[2]), "r"((a)[3]), \
                   "r"((b)[0]), "r"((b)[1]))

// ---------------------------------------------------------------------------
// Weight prep: Wt_hi/lo[mat][n][k] = bf16 split of W[k][n]
// ---------------------------------------------------------------------------
__global__ void prep_w_kernel(const float* __restrict__ Wq, const float* __restrict__ Wk,
                              const float* __restrict__ Wv, const float* __restrict__ Wo)
{
    const int mat = blockIdx.y;
    const float* W = (mat == 0) ? Wq : (mat == 1) ? Wk : (mat == 2) ? Wv : Wo;
    const int n = blockIdx.x;
    const int k = threadIdx.x;
    float f = W[k * 256 + n];
    __nv_bfloat16 h = __float2bfloat16(f);
    float l = f - __bfloat162float(h);
    g_Wth[mat * 65536 + n * 256 + k] = h;
    g_Wtl[mat * 65536 + n * 256 + k] = __float2bfloat16(l);
}

// ---------------------------------------------------------------------------
// HMMA bf16 split-3 GEMM: C[16384,256] = A[16384,256] @ W[256,256] + bias
//   W pre-transposed & split: Wth/Wtl[n][k] (col-major B for row.col mma)
//   BM=64, BN=128, BK=32, 256 threads (8 warps: 2m x 4n; warp tile 32x32).
//   grid (2, 256) = 512 blocks -> ~3 blocks/SM.
//   Split-3: Ah*Wh + Ah*Wl + Al*Wh, fp32 accumulate.
//   Smem rows padded to 80B: ldmatrix lane addrs r*80+16c cover all banks.
// ---------------------------------------------------------------------------
#define AH_OFF 0
#define AL_OFF 5120
#define WH_OFF 10240
#define WL_OFF 20480
#define GSMEM  30720

__device__ __forceinline__ void store_pair(float* C, size_t idx, float x, float y) {
    float2 o; o.x = x; o.y = y;
    *(float2*)&C[idx] = o;
}
__device__ __forceinline__ void store_pair(__half* C, size_t idx, float x, float y) {
    *(__half2*)&C[idx] = __floats2half2_rn(x, y);
}

template <typename OutT>
__global__ void __launch_bounds__(256) gemm_tc_kernel(
    const float* __restrict__ A,
    const __nv_bfloat16* __restrict__ Wth,
    const __nv_bfloat16* __restrict__ Wtl,
    const float* __restrict__ bias,
    OutT* __restrict__ C)
{
    __shared__ __align__(16) char smem[GSMEM];
    const uint32_t sb = smem_to_u32(smem);

    const int tid    = threadIdx.x;
    const int lane   = tid & 31;
    const int wid    = tid >> 5;
    const int warp_m = wid & 1;      // 2 warps along M
    const int warp_n = wid >> 1;     // 4 warps along N
    const int m0     = blockIdx.y * 64;
    const int n0     = blockIdx.x * 128;

    float acc[2][4][4];
    #pragma unroll
    for (int mt = 0; mt < 2; mt++)
        #pragma unroll
        for (int nt = 0; nt < 4; nt++)
            #pragma unroll
            for (int i = 0; i < 4; i++) acc[mt][nt][i] = 0.f;

    // A staging: thread -> (row = tid>>2, 8 k-values at (tid&3)*8)
    const int sa_r = tid >> 2;
    const int sa_k = (tid & 3) * 8;
    // W staging: thread -> (row = tid>>1, 16 k-values at (tid&1)*16)
    const int sw_r = tid >> 1;
    const int sw_k = (tid & 1) * 16;

    for (int c = 0; c < 8; c++) {
        const int k0 = c * 32;

        // ---- stage A chunk (64 x 32) as bf16 hi/lo ----
        {
            const float* ap = &A[(size_t)(m0 + sa_r) * DMODEL + k0 + sa_k];
            float4 f0 = *(const float4*)(ap + 0);
            float4 f1 = *(const float4*)(ap + 4);
            float v[8];
            v[0]=f0.x; v[1]=f0.y; v[2]=f0.z; v[3]=f0.w;
            v[4]=f1.x; v[5]=f1.y; v[6]=f1.z; v[7]=f1.w;
            uint32_t hi[4], lo[4];
            #pragma unroll
            for (int i = 0; i < 4; i++) {
                float x = v[2*i], y = v[2*i+1];
                __nv_bfloat16 hx = __float2bfloat16(x);
                __nv_bfloat16 hy = __float2bfloat16(y);
                __nv_bfloat162 hp; hp.x = hx; hp.y = hy;
                hi[i] = *reinterpret_cast<uint32_t*>(&hp);
                __nv_bfloat162 lp;
                lp.x = __float2bfloat16(x - __bfloat162float(hx));
                lp.y = __float2bfloat16(y - __bfloat162float(hy));
                lo[i] = *reinterpret_cast<uint32_t*>(&lp);
            }
            char* dh = smem + AH_OFF + sa_r * 80 + sa_k * 2;
            char* dl = smem + AL_OFF + sa_r * 80 + sa_k * 2;
            uint4 u;
            u.x=hi[0]; u.y=hi[1]; u.z=hi[2]; u.w=hi[3]; *(uint4*)dh = u;
            u.x=lo[0]; u.y=lo[1]; u.z=lo[2]; u.w=lo[3]; *(uint4*)dl = u;
        }

        // ---- stage W chunk (128 n-rows x 32 k) bf16 hi/lo ----
        {
            const __nv_bfloat16* wh = &Wth[(size_t)(n0 + sw_r) * DMODEL + k0 + sw_k];
            const __nv_bfloat16* wl = &Wtl[(size_t)(n0 + sw_r) * DMODEL + k0 + sw_k];
            uint4 h0 = *(const uint4*)(wh);
            uint4 h1 = *(const uint4*)(wh + 8);
            uint4 l0 = *(const uint4*)(wl);
            uint4 l1 = *(const uint4*)(wl + 8);
            char* dh = smem + WH_OFF + sw_r * 80 + sw_k * 2;
            char* dl = smem + WL_OFF + sw_r * 80 + sw_k * 2;
            *(uint4*)(dh)      = h0;
            *(uint4*)(dh + 16) = h1;
            *(uint4*)(dl)      = l0;
            *(uint4*)(dl + 16) = l1;
        }

        __syncthreads();

        // ---- compute: 2 k-steps of 16 ----
        #pragma unroll
        for (int ks = 0; ks < 2; ks++) {
            const int aidx = lane >> 3;
            const int a_m  = (aidx & 1) * 8 + (lane & 7);
            const int a_k  = (aidx >> 1) * 8;
            uint32_t ah[2][4], al[2][4];
            #pragma unroll
            for (int mt = 0; mt < 2; mt++) {
                const uint32_t row = (uint32_t)(warp_m * 32 + mt * 16 + a_m);
                const uint32_t col = (uint32_t)(ks * 16 + a_k) * 2u;
                LDMATRIX_X4(ah[mt][0], ah[mt][1], ah[mt][2], ah[mt][3],
                            sb + AH_OFF + row * 80u + col);
                LDMATRIX_X4(al[mt][0], al[mt][1], al[mt][2], al[mt][3],
                            sb + AL_OFF + row * 80u + col);
            }
            const int l2  = lane & 15;
            const int b_n = l2 & 7;
            const int b_k = (l2 >> 3) * 8;
            uint32_t bh[4][2], bl[4][2];
            #pragma unroll
            for (int nt = 0; nt < 4; nt++) {
                const uint32_t row = (uint32_t)(warp_n * 32 + nt * 8 + b_n);
                const uint32_t col = (uint32_t)(ks * 16 + b_k) * 2u;
                LDMATRIX_X2(bh[nt][0], bh[nt][1], sb + WH_OFF + row * 80u + col);
                LDMATRIX_X2(bl[nt][0], bl[nt][1], sb + WL_OFF + row * 80u + col);
            }
            #pragma unroll
            for (int mt = 0; mt < 2; mt++) {
                #pragma unroll
                for (int nt = 0; nt < 4; nt++) {
                    MMA_BF16(acc[mt][nt], ah[mt], bh[nt]);
                    MMA_BF16(acc[mt][nt], ah[mt], bl[nt]);
                    MMA_BF16(acc[mt][nt], al[mt], bh[nt]);
                }
            }
        }
        __syncthreads();
    }

    // ---- epilogue: bias + store ----
    const int gr = lane >> 2;
    const int gc = (lane & 3) * 2;
    #pragma unroll
    for (int mt = 0; mt < 2; mt++) {
        const int mrow = m0 + warp_m * 32 + mt * 16 + gr;
        #pragma unroll
        for (int nt = 0; nt < 4; nt++) {
            const int ncol = n0 + warp_n * 32 + nt * 8 + gc;
            const float2 bv = *(const float2*)&bias[ncol];
            store_pair(C, (size_t)mrow * DMODEL + ncol,
                       acc[mt][nt][0] + bv.x, acc[mt][nt][1] + bv.y);
            store_pair(C, (size_t)(mrow + 8) * DMODEL + ncol,
                       acc[mt][nt][2] + bv.x, acc[mt][nt][3] + bv.y);
        }
    }
}

// ---------------------------------------------------------------------------
// kNN attention, fp16 K/V gather: one block per query, 8 warps.
// Phase 1: warp w -> neighbours 4w..4w+3; lane d -> dims [8d,8d+8) (fp16,
//          16B per lane -> 512B/row = 4 wavefronts). Quad-reduce -> Es[j][h].
// Phase 2: warp h softmax over 32 scores; weights -> As[h][j].
// Phase 3: warp w -> head pair hp=w&3 (heads 2hp,2hp+1), group grp=w>>2
//          (neighbours grp*16..+16). Lane loads __half2 -> 128B/warp/neighbour
//          full wavefront. Cross-group partials combined via smem.
// ---------------------------------------------------------------------------
__global__ void __launch_bounds__(256) knn_attn_kernel(const int* __restrict__ nb)
{
    __shared__ float Es[32][9];
    __shared__ float As[8][33];
    __shared__ float Vred[4][64];
    __shared__ int   s_row[32];

    const int tid  = threadIdx.x;
    const int q    = blockIdx.x;
    const int b    = q >> 13;
    const int w    = tid >> 5;
    const int lane = tid & 31;

    if (tid < 32) s_row[tid] = (b << 13) + nb[(size_t)q * 32 + tid];
    __syncthreads();

    // ---- Phase 1: scores ----
    {
        const float4* qp = (const float4*)&g_Qh[(size_t)q * DMODEL + lane * 8];
        float4 q0 = qp[0];
        float4 q1 = qp[1];

        #pragma unroll
        for (int i = 0; i < 4; i++) {
            const int j   = w * 4 + i;
            const int row = s_row[j];
            uint4 kv = *(const uint4*)&g_Khh[(size_t)row * DMODEL + lane * 8];
            float2 f0 = __half22float2(*reinterpret_cast<__half2*>(&kv.x));
            float2 f1 = __half22float2(*reinterpret_cast<__half2*>(&kv.y));
            float2 f2 = __half22float2(*reinterpret_cast<__half2*>(&kv.z));
            float2 f3 = __half22float2(*reinterpret_cast<__half2*>(&kv.w));
            float p = q0.x * f0.x;
            p = fmaf(q0.y, f0.y, p);
            p = fmaf(q0.z, f1.x, p);
            p = fmaf(q0.w, f1.y, p);
            p = fmaf(q1.x, f2.x, p);
            p = fmaf(q1.y, f2.y, p);
            p = fmaf(q1.z, f3.x, p);
            p = fmaf(q1.w, f3.y, p);
            p += __shfl_xor_sync(0xffffffffu, p, 1);
            p += __shfl_xor_sync(0xffffffffu, p, 2);
            if ((lane & 3) == 0) Es[j][lane >> 2] = p * 0.0625f;  // 1/sqrt(256)
        }
    }
    __syncthreads();

    // ---- Phase 2: softmax (warp h over its 32 neighbour scores) ----
    {
        const int h = w;
        float e = Es[lane][h];
        float m = e;
        #pragma unroll
        for (int o = 16; o > 0; o >>= 1)
            m = fmaxf(m, __shfl_xor_sync(0xffffffffu, m, o));
        float p = __expf(e - m);
        float s = p;
        #pragma unroll
        for (int o = 16; o > 0; o >>= 1)
            s += __shfl_xor_sync(0xffffffffu, s, o);
        As[h][lane] = p / s;
    }
    __syncthreads();

    // ---- Phase 3: AV ----
    {
        const int hp  = w & 3;         // head pair: heads 2hp, 2hp+1
        const int grp = w >> 2;        // neighbour group
        const int hl  = hp * 2 + (lane >> 4);
        const int col = hp * 64 + lane * 2;

        float ax = 0.f, ay = 0.f;
        #pragma unroll
        for (int jj = 0; jj < 16; jj++) {
            const int j   = grp * 16 + jj;
            const int row = s_row[j];
            __half2 v = *(const __half2*)&g_Vhh[(size_t)row * DMODEL + col];
            float2 vf = __half22float2(v);
            const float aj = As[hl][j];
            ax = fmaf(aj, vf.x, ax);
            ay = fmaf(aj, vf.y, ay);
        }
        if (grp == 1) {
            Vred[hp][lane * 2 + 0] = ax;
            Vred[hp][lane * 2 + 1] = ay;
        }
        __syncthreads();
        if (grp == 0) {
            ax += Vred[hp][lane * 2 + 0];
            ay += Vred[hp][lane * 2 + 1];
            float2 o; o.x = ax; o.y = ay;
            *(float2*)&g_AV[(size_t)q * DMODEL + col] = o;
        }
    }
}

// ---------------------------------------------------------------------------
extern "C" void kernel_launch(void* const* d_in, const int* in_sizes, int n_in,
                              void* d_out, int out_size)
{
    const float* Q  = (const float*)d_in[0];
    const float* K  = (const float*)d_in[1];
    const int*   nb = (const int*)d_in[2];
    const float* Wq = (const float*)d_in[3];
    const float* bq = (const float*)d_in[4];
    const float* Wk = (const float*)d_in[5];
    const float* bk = (const float*)d_in[6];
    const float* Wv = (const float*)d_in[7];
    const float* bv = (const float*)d_in[8];
    const float* Wo = (const float*)d_in[9];
    const float* bo = (const float*)d_in[10];
    float* out = (float*)d_out;

    float* Qh = 0;
    float* AV = 0;
    __half* Khh = 0;
    __half* Vhh = 0;
    __nv_bfloat16* Wth = 0;
    __nv_bfloat16* Wtl = 0;
    cudaGetSymbolAddress((void**)&Qh, g_Qh);
    cudaGetSymbolAddress((void**)&AV, g_AV);
    cudaGetSymbolAddress((void**)&Khh, g_Khh);
    cudaGetSymbolAddress((void**)&Vhh, g_Vhh);
    cudaGetSymbolAddress((void**)&Wth, g_Wth);
    cudaGetSymbolAddress((void**)&Wtl, g_Wtl);

    // weight transpose + bf16 split (mat order: 0=Wq, 1=Wk, 2=Wv, 3=Wo)
    dim3 pgrid(256, 4);
    prep_w_kernel<<<pgrid, 256>>>(Wq, Wk, Wv, Wo);

    dim3 ggrid(2, 256);
    gemm_tc_kernel<__half><<<ggrid, 256>>>(K, Wth + 65536, Wtl + 65536, bk, Khh);
    gemm_tc_kernel<__half><<<ggrid, 256>>>(K, Wth + 2 * 65536, Wtl + 2 * 65536, bv, Vhh);
    gemm_tc_kernel<float><<<ggrid, 256>>>(Q, Wth, Wtl, bq, Qh);

    knn_attn_kernel<<<16384, 256>>>(nb);

    gemm_tc_kernel<float><<<ggrid, 256>>>(AV, Wth + 3 * 65536, Wtl + 3 * 65536, bo, out);
}

// round 9
// speedup vs baseline: 1.2016x; 1.2016x over previous
#include <cuda_runtime.h>
#include <cuda_bf16.h>
#include <cuda_fp16.h>
#include <cstdint>

#define ROWS_TOTAL 16384
#define DMODEL 256

// ---------------------------------------------------------------------------
// Scratch (static device arrays — no allocation in kernel_launch).
// ---------------------------------------------------------------------------
__device__ __align__(16) float  g_Qh[ROWS_TOTAL * DMODEL];
__device__ __align__(16) float  g_AV[ROWS_TOTAL * DMODEL];
__device__ __align__(16) __half g_Khh[ROWS_TOTAL * DMODEL];
__device__ __align__(16) __half g_Vhh[ROWS_TOTAL * DMODEL];
// Transposed + bf16-split weights: [mat][N=256][K=256]
__device__ __align__(16) __nv_bfloat16 g_Wth[4 * 65536];
__device__ __align__(16) __nv_bfloat16 g_Wtl[4 * 65536];

// ---------------------------------------------------------------------------
// Warp-level tensor-core primitives (base-target: ldmatrix sm_75+, bf16 mma sm_80+)
// ---------------------------------------------------------------------------
__device__ __forceinline__ uint32_t smem_to_u32(const void* smem_ptr) {
    uint32_t addr;
    asm("{ .reg .u64 tmp; cvta.to.shared.u64 tmp, %1; cvt.u32.u64 %0, tmp; }"
        : "=r"(addr) : "l"(smem_ptr));
    return addr;
}

#define LDMATRIX_X4(r0, r1, r2, r3, addr) \
    asm volatile("ldmatrix.sync.aligned.m8n8.x4.shared.b16 {%0,%1,%2,%3}, [%4];" \
                 : "=r"(r0), "=r"(r1), "=r"(r2), "=r"(r3) : "r"(addr))

#define LDMATRIX_X2(r0, r1, addr) \
    asm volatile("ldmatrix.sync.aligned.m8n8.x2.shared.b16 {%0,%1}, [%2];" \
                 : "=r"(r0), "=r"(r1) : "r"(addr))

#define MMA_BF16(d, a, b) \
    asm volatile("mma.sync.aligned.m16n8k16.row.col.f32.bf16.bf16.f32 " \
                 "{%0,%1,%2,%3}, {%4,%5,%6,%7}, {%8,%9}, {%0,%1,%2,%3};" \
                 : "+f"((d)[0]), "+f"((d)[1]), "+f"((d)[2]), "+f"((d)[3]) \
                 : "r"((a)[0]), "r"((a)[1]), "r"((a)[2]), "r"((a)[3]), \
                   "r"((b)[0]), "r"((b)[1]))

// ---------------------------------------------------------------------------
// Weight prep: Wt_hi/lo[mat][n][k] = bf16 split of W[k][n]
// ---------------------------------------------------------------------------
__global__ void prep_w_kernel(const float* __restrict__ Wq, const float* __restrict__ Wk,
                              const float* __restrict__ Wv, const float* __restrict__ Wo)
{
    const int mat = blockIdx.y;
    const float* W = (mat == 0) ? Wq : (mat == 1) ? Wk : (mat == 2) ? Wv : Wo;
    const int n = blockIdx.x;
    const int k = threadIdx.x;
    float f = W[k * 256 + n];
    __nv_bfloat16 h = __float2bfloat16(f);
    float l = f - __bfloat162float(h);
    g_Wth[mat * 65536 + n * 256 + k] = h;
    g_Wtl[mat * 65536 + n * 256 + k] = __float2bfloat16(l);
}

// ---------------------------------------------------------------------------
// HMMA bf16 split-3 GEMM, double-buffered pipeline.
// C[16384,256] = A[16384,256] @ W[256,256] + bias
//   W pre-transposed & split: Wth/Wtl[n][k] (col-major B for row.col mma)
//   BM=128, BN=128, BK=32, 256 threads (8 warps: 4m x 2n; warp tile 32x64).
//   Pipeline: prefetch chunk c+1 globals into regs during chunk c MMAs,
//   convert+store into alternate smem buffer; ONE sync per iteration.
//   Split-3: Ah*Wh + Ah*Wl + Al*Wh, fp32 accumulate.
//   Smem rows padded to 80B: ldmatrix lane addrs r*80+16c cover all banks.
// ---------------------------------------------------------------------------
#define AH_OFF 0
#define AL_OFF 10240
#define WH_OFF 20480
#define WL_OFF 30720
#define BUF_SZ 40960
#define GSMEM  (2 * BUF_SZ)

__device__ __forceinline__ void store_pair(float* C, size_t idx, float x, float y) {
    float2 o; o.x = x; o.y = y;
    *(float2*)&C[idx] = o;
}
__device__ __forceinline__ void store_pair(__half* C, size_t idx, float x, float y) {
    *(__half2*)&C[idx] = __floats2half2_rn(x, y);
}

// Convert 16 fp32 -> hi/lo bf16x2 pairs and store 2x16B each into smem.
__device__ __forceinline__ void cvt_store_a(char* dh, char* dl, const float* v) {
    uint32_t hi[8], lo[8];
    #pragma unroll
    for (int i = 0; i < 8; i++) {
        float x = v[2 * i], y = v[2 * i + 1];
        __nv_bfloat16 hx = __float2bfloat16(x);
        __nv_bfloat16 hy = __float2bfloat16(y);
        __nv_bfloat162 hp; hp.x = hx; hp.y = hy;
        hi[i] = *reinterpret_cast<uint32_t*>(&hp);
        __nv_bfloat162 lp;
        lp.x = __float2bfloat16(x - __bfloat162float(hx));
        lp.y = __float2bfloat16(y - __bfloat162float(hy));
        lo[i] = *reinterpret_cast<uint32_t*>(&lp);
    }
    uint4 u;
    u.x=hi[0]; u.y=hi[1]; u.z=hi[2]; u.w=hi[3]; *(uint4*)(dh)      = u;
    u.x=hi[4]; u.y=hi[5]; u.z=hi[6]; u.w=hi[7]; *(uint4*)(dh + 16) = u;
    u.x=lo[0]; u.y=lo[1]; u.z=lo[2]; u.w=lo[3]; *(uint4*)(dl)      = u;
    u.x=lo[4]; u.y=lo[5]; u.z=lo[6]; u.w=lo[7]; *(uint4*)(dl + 16) = u;
}

template <typename OutT>
__global__ void __launch_bounds__(256, 1) gemm_tc_kernel(
    const float* __restrict__ A,
    const __nv_bfloat16* __restrict__ Wth,
    const __nv_bfloat16* __restrict__ Wtl,
    const float* __restrict__ bias,
    OutT* __restrict__ C)
{
    extern __shared__ __align__(16) char smem[];
    const uint32_t sb = smem_to_u32(smem);

    const int tid    = threadIdx.x;
    const int lane   = tid & 31;
    const int wid    = tid >> 5;
    const int warp_m = wid & 3;      // 4 warps along M
    const int warp_n = wid >> 2;     // 2 warps along N
    const int m0     = blockIdx.y * 128;
    const int n0     = blockIdx.x * 128;

    float acc[2][8][4];
    #pragma unroll
    for (int mt = 0; mt < 2; mt++)
        #pragma unroll
        for (int nt = 0; nt < 8; nt++)
            #pragma unroll
            for (int i = 0; i < 4; i++) acc[mt][nt][i] = 0.f;

    // staging indices (each thread: one row, 16 k-values = 64B)
    const int st_r    = tid >> 1;        // 0..127
    const int st_koff = (tid & 1) * 16;  // 0 or 16
    const float* a_base = &A[(size_t)(m0 + st_r) * DMODEL + st_koff];
    const __nv_bfloat16* wh_base = &Wth[(size_t)(n0 + st_r) * DMODEL + st_koff];
    const __nv_bfloat16* wl_base = &Wtl[(size_t)(n0 + st_r) * DMODEL + st_koff];
    const int st_off = st_r * 80 + st_koff * 2;

    // ---- prologue: stage chunk 0 into buffer 0 ----
    {
        float v[16];
        #pragma unroll
        for (int i = 0; i < 4; i++)
            *(float4*)&v[i * 4] = *(const float4*)(a_base + i * 4);
        cvt_store_a(smem + AH_OFF + st_off, smem + AL_OFF + st_off, v);
        uint4 h0 = *(const uint4*)(wh_base);
        uint4 h1 = *(const uint4*)(wh_base + 8);
        uint4 l0 = *(const uint4*)(wl_base);
        uint4 l1 = *(const uint4*)(wl_base + 8);
        *(uint4*)(smem + WH_OFF + st_off)      = h0;
        *(uint4*)(smem + WH_OFF + st_off + 16) = h1;
        *(uint4*)(smem + WL_OFF + st_off)      = l0;
        *(uint4*)(smem + WL_OFF + st_off + 16) = l1;
    }
    __syncthreads();

    for (int c = 0; c < 8; c++) {
        // ---- prefetch chunk c+1 globals into registers ----
        float pa[16];
        uint4 pwh0, pwh1, pwl0, pwl1;
        if (c < 7) {
            const int k1 = (c + 1) * 32;
            #pragma unroll
            for (int i = 0; i < 4; i++)
                *(float4*)&pa[i * 4] = *(const float4*)(a_base + k1 + i * 4);
            pwh0 = *(const uint4*)(wh_base + k1);
            pwh1 = *(const uint4*)(wh_base + k1 + 8);
            pwl0 = *(const uint4*)(wl_base + k1);
            pwl1 = *(const uint4*)(wl_base + k1 + 8);
        }

        // ---- compute chunk c from buffer c&1 ----
        const uint32_t bb = sb + (uint32_t)((c & 1) * BUF_SZ);
        #pragma unroll
        for (int ks = 0; ks < 2; ks++) {
            const int aidx = lane >> 3;
            const int a_m  = (aidx & 1) * 8 + (lane & 7);
            const int a_k  = (aidx >> 1) * 8;
            uint32_t ah[2][4], al[2][4];
            #pragma unroll
            for (int mt = 0; mt < 2; mt++) {
                const uint32_t row = (uint32_t)(warp_m * 32 + mt * 16 + a_m);
                const uint32_t col = (uint32_t)(ks * 16 + a_k) * 2u;
                LDMATRIX_X4(ah[mt][0], ah[mt][1], ah[mt][2], ah[mt][3],
                            bb + AH_OFF + row * 80u + col);
                LDMATRIX_X4(al[mt][0], al[mt][1], al[mt][2], al[mt][3],
                            bb + AL_OFF + row * 80u + col);
            }
            const int l2  = lane & 15;
            const int b_n = l2 & 7;
            const int b_k = (l2 >> 3) * 8;
            uint32_t bh[8][2], bl[8][2];
            #pragma unroll
            for (int nt = 0; nt < 8; nt++) {
                const uint32_t row = (uint32_t)(warp_n * 64 + nt * 8 + b_n);
                const uint32_t col = (uint32_t)(ks * 16 + b_k) * 2u;
                LDMATRIX_X2(bh[nt][0], bh[nt][1], bb + WH_OFF + row * 80u + col);
                LDMATRIX_X2(bl[nt][0], bl[nt][1], bb + WL_OFF + row * 80u + col);
            }
            #pragma unroll
            for (int mt = 0; mt < 2; mt++) {
                #pragma unroll
                for (int nt = 0; nt < 8; nt++) {
                    MMA_BF16(acc[mt][nt], ah[mt], bh[nt]);
                    MMA_BF16(acc[mt][nt], ah[mt], bl[nt]);
                    MMA_BF16(acc[mt][nt], al[mt], bh[nt]);
                }
            }
        }

        // ---- store prefetched chunk into the OTHER buffer (no pre-sync:
        //      that buffer was last read in iter c-1, drained by last sync) ----
        if (c < 7) {
            char* ob = smem + ((c + 1) & 1) * BUF_SZ;
            cvt_store_a(ob + AH_OFF + st_off, ob + AL_OFF + st_off, pa);
            *(uint4*)(ob + WH_OFF + st_off)      = pwh0;
            *(uint4*)(ob + WH_OFF + st_off + 16) = pwh1;
            *(uint4*)(ob + WL_OFF + st_off)      = pwl0;
            *(uint4*)(ob + WL_OFF + st_off + 16) = pwl1;
        }
        __syncthreads();
    }

    // ---- epilogue: bias + store ----
    const int gr = lane >> 2;
    const int gc = (lane & 3) * 2;
    #pragma unroll
    for (int mt = 0; mt < 2; mt++) {
        const int mrow = m0 + warp_m * 32 + mt * 16 + gr;
        #pragma unroll
        for (int nt = 0; nt < 8; nt++) {
            const int ncol = n0 + warp_n * 64 + nt * 8 + gc;
            const float2 bv = *(const float2*)&bias[ncol];
            store_pair(C, (size_t)mrow * DMODEL + ncol,
                       acc[mt][nt][0] + bv.x, acc[mt][nt][1] + bv.y);
            store_pair(C, (size_t)(mrow + 8) * DMODEL + ncol,
                       acc[mt][nt][2] + bv.x, acc[mt][nt][3] + bv.y);
        }
    }
}

// ---------------------------------------------------------------------------
// kNN attention, fp16 K/V gather (unchanged from round 8).
// ---------------------------------------------------------------------------
__global__ void __launch_bounds__(256) knn_attn_kernel(const int* __restrict__ nb)
{
    __shared__ float Es[32][9];
    __shared__ float As[8][33];
    __shared__ float Vred[4][64];
    __shared__ int   s_row[32];

    const int tid  = threadIdx.x;
    const int q    = blockIdx.x;
    const int b    = q >> 13;
    const int w    = tid >> 5;
    const int lane = tid & 31;

    if (tid < 32) s_row[tid] = (b << 13) + nb[(size_t)q * 32 + tid];
    __syncthreads();

    // ---- Phase 1: scores ----
    {
        const float4* qp = (const float4*)&g_Qh[(size_t)q * DMODEL + lane * 8];
        float4 q0 = qp[0];
        float4 q1 = qp[1];

        #pragma unroll
        for (int i = 0; i < 4; i++) {
            const int j   = w * 4 + i;
            const int row = s_row[j];
            uint4 kv = *(const uint4*)&g_Khh[(size_t)row * DMODEL + lane * 8];
            float2 f0 = __half22float2(*reinterpret_cast<__half2*>(&kv.x));
            float2 f1 = __half22float2(*reinterpret_cast<__half2*>(&kv.y));
            float2 f2 = __half22float2(*reinterpret_cast<__half2*>(&kv.z));
            float2 f3 = __half22float2(*reinterpret_cast<__half2*>(&kv.w));
            float p = q0.x * f0.x;
            p = fmaf(q0.y, f0.y, p);
            p = fmaf(q0.z, f1.x, p);
            p = fmaf(q0.w, f1.y, p);
            p = fmaf(q1.x, f2.x, p);
            p = fmaf(q1.y, f2.y, p);
            p = fmaf(q1.z, f3.x, p);
            p = fmaf(q1.w, f3.y, p);
            p += __shfl_xor_sync(0xffffffffu, p, 1);
            p += __shfl_xor_sync(0xffffffffu, p, 2);
            if ((lane & 3) == 0) Es[j][lane >> 2] = p * 0.0625f;  // 1/sqrt(256)
        }
    }
    __syncthreads();

    // ---- Phase 2: softmax (warp h over its 32 neighbour scores) ----
    {
        const int h = w;
        float e = Es[lane][h];
        float m = e;
        #pragma unroll
        for (int o = 16; o > 0; o >>= 1)
            m = fmaxf(m, __shfl_xor_sync(0xffffffffu, m, o));
        float p = __expf(e - m);
        float s = p;
        #pragma unroll
        for (int o = 16; o > 0; o >>= 1)
            s += __shfl_xor_sync(0xffffffffu, s, o);
        As[h][lane] = p / s;
    }
    __syncthreads();

    // ---- Phase 3: AV ----
    {
        const int hp  = w & 3;         // head pair: heads 2hp, 2hp+1
        const int grp = w >> 2;        // neighbour group
        const int hl  = hp * 2 + (lane >> 4);
        const int col = hp * 64 + lane * 2;

        float ax = 0.f, ay = 0.f;
        #pragma unroll
        for (int jj = 0; jj < 16; jj++) {
            const int j   = grp * 16 + jj;
            const int row = s_row[j];
            __half2 v = *(const __half2*)&g_Vhh[(size_t)row * DMODEL + col];
            float2 vf = __half22float2(v);
            const float aj = As[hl][j];
            ax = fmaf(aj, vf.x, ax);
            ay = fmaf(aj, vf.y, ay);
        }
        if (grp == 1) {
            Vred[hp][lane * 2 + 0] = ax;
            Vred[hp][lane * 2 + 1] = ay;
        }
        __syncthreads();
        if (grp == 0) {
            ax += Vred[hp][lane * 2 + 0];
            ay += Vred[hp][lane * 2 + 1];
            float2 o; o.x = ax; o.y = ay;
            *(float2*)&g_AV[(size_t)q * DMODEL + col] = o;
        }
    }
}

// ---------------------------------------------------------------------------
extern "C" void kernel_launch(void* const* d_in, const int* in_sizes, int n_in,
                              void* d_out, int out_size)
{
    const float* Q  = (const float*)d_in[0];
    const float* K  = (const float*)d_in[1];
    const int*   nb = (const int*)d_in[2];
    const float* Wq = (const float*)d_in[3];
    const float* bq = (const float*)d_in[4];
    const float* Wk = (const float*)d_in[5];
    const float* bk = (const float*)d_in[6];
    const float* Wv = (const float*)d_in[7];
    const float* bv = (const float*)d_in[8];
    const float* Wo = (const float*)d_in[9];
    const float* bo = (const float*)d_in[10];
    float* out = (float*)d_out;

    float* Qh = 0;
    float* AV = 0;
    __half* Khh = 0;
    __half* Vhh = 0;
    __nv_bfloat16* Wth = 0;
    __nv_bfloat16* Wtl = 0;
    cudaGetSymbolAddress((void**)&Qh, g_Qh);
    cudaGetSymbolAddress((void**)&AV, g_AV);
    cudaGetSymbolAddress((void**)&Khh, g_Khh);
    cudaGetSymbolAddress((void**)&Vhh, g_Vhh);
    cudaGetSymbolAddress((void**)&Wth, g_Wth);
    cudaGetSymbolAddress((void**)&Wtl, g_Wtl);

    cudaFuncSetAttribute(gemm_tc_kernel<float>,
                         cudaFuncAttributeMaxDynamicSharedMemorySize, GSMEM);
    cudaFuncSetAttribute(gemm_tc_kernel<__half>,
                         cudaFuncAttributeMaxDynamicSharedMemorySize, GSMEM);

    // weight transpose + bf16 split (mat order: 0=Wq, 1=Wk, 2=Wv, 3=Wo)
    dim3 pgrid(256, 4);
    prep_w_kernel<<<pgrid, 256>>>(Wq, Wk, Wv, Wo);

    dim3 ggrid(2, 128);
    gemm_tc_kernel<__half><<<ggrid, 256, GSMEM>>>(K, Wth + 65536, Wtl + 65536, bk, Khh);
    gemm_tc_kernel<__half><<<ggrid, 256, GSMEM>>>(K, Wth + 2 * 65536, Wtl + 2 * 65536, bv, Vhh);
    gemm_tc_kernel<float><<<ggrid, 256, GSMEM>>>(Q, Wth, Wtl, bq, Qh);

    knn_attn_kernel<<<16384, 256>>>(nb);

    gemm_tc_kernel<float><<<ggrid, 256, GSMEM>>>(AV, Wth + 3 * 65536, Wtl + 3 * 65536, bo, out);
}